// round 14
// baseline (speedup 1.0000x reference)
#include <cuda_runtime.h>
#include <cuda_fp16.h>

#define NV 100000
#define NL 8

// P table in fp16: 16 B/row -> one LDG.128 per gather. 1.6 MB, L2-resident.
__device__ __align__(256) __half g_Ph[NV * NL];

// ---------------------------------------------------------------------------
__device__ __forceinline__ float block_reduce(float v) {
    v += __shfl_xor_sync(0xffffffffu, v, 16);
    v += __shfl_xor_sync(0xffffffffu, v, 8);
    v += __shfl_xor_sync(0xffffffffu, v, 4);
    v += __shfl_xor_sync(0xffffffffu, v, 2);
    v += __shfl_xor_sync(0xffffffffu, v, 1);
    __shared__ float s[8];
    int w = threadIdx.x >> 5;
    if ((threadIdx.x & 31) == 0) s[w] = v;
    __syncthreads();
    if (threadIdx.x < 8) {
        v = s[threadIdx.x];
        v += __shfl_xor_sync(0xffu, v, 4);
        v += __shfl_xor_sync(0xffu, v, 2);
        v += __shfl_xor_sync(0xffu, v, 1);
    }
    return v;
}

__device__ __forceinline__ uint4 load_row_raw(int v) {
    return __ldg(reinterpret_cast<const uint4*>(g_Ph + (size_t)v * NL));
}

__device__ __forceinline__ void row_to_f(const uint4& u, float* f) {
    float2 a = __half22float2(*reinterpret_cast<const __half2*>(&u.x));
    float2 b = __half22float2(*reinterpret_cast<const __half2*>(&u.y));
    float2 c = __half22float2(*reinterpret_cast<const __half2*>(&u.z));
    float2 d = __half22float2(*reinterpret_cast<const __half2*>(&u.w));
    f[0] = a.x; f[1] = a.y; f[2] = b.x; f[3] = b.y;
    f[4] = c.x; f[5] = c.y; f[6] = d.x; f[7] = d.y;
}

__device__ __forceinline__ float dot8(const uint4& pu, const uint4& qu) {
    float p[NL], q[NL];
    row_to_f(pu, p); row_to_f(qu, q);
    float d = 0.f;
#pragma unroll
    for (int t = 0; t < NL; t++) d = fmaf(p[t], q[t], d);
    return d;
}

// tri contribution = -4*(p.q + p.r + q.r) + (16/3)*sum_a p_a q_a r_a
__device__ __forceinline__ float tri_term(const uint4& pu, const uint4& qu,
                                          const uint4& ru) {
    float p[NL], q[NL], r[NL];
    row_to_f(pu, p); row_to_f(qu, q); row_to_f(ru, r);
    float s = 0.f, C = 0.f;
#pragma unroll
    for (int t = 0; t < NL; t++) {
        float qr = q[t] * r[t];
        s = fmaf(p[t], q[t] + r[t], s) + qr;
        C = fmaf(p[t], qr, C);
    }
    return fmaf(-4.f, s, (16.f / 3.f) * C);
}

// ---------------------------------------------------------------------------
// Build P = softmax(full, axis=1) in fp16 via h2exp2 (measured-best shape:
// 256 threads/block). Thread 0 seeds out = 2E+8T.
__global__ __launch_bounds__(256)
void build_P(const float* __restrict__ trainable,
             const float* __restrict__ fixedp,
             const int*   __restrict__ fidx,
             int n_fixed, float* __restrict__ out, float base) {
    int v = blockIdx.x * blockDim.x + threadIdx.x;
    if (v == 0) out[0] = base;
    if (v >= NV) return;

    int f0 = __ldg(&fidx[0]);
    int fl = __ldg(&fidx[n_fixed - 1]);
    int lo;
    bool is_fixed;
    if (fl - f0 == n_fixed - 1) {          // contiguous block of fixed ids
        is_fixed = (v >= f0) && (v <= fl);
        lo = is_fixed ? (v - f0) : ((v < f0) ? 0 : n_fixed);
    } else {                               // general sorted unique set
        lo = 0; int hi = n_fixed;
        while (lo < hi) {
            int mid = (lo + hi) >> 1;
            if (__ldg(&fidx[mid]) < v) lo = mid + 1; else hi = mid;
        }
        is_fixed = (lo < n_fixed) && (__ldg(&fidx[lo]) == v);
    }
    const float4* src = reinterpret_cast<const float4*>(
        is_fixed ? (fixedp + (size_t)lo * NL)
                 : (trainable + (size_t)(v - lo) * NL));

    float4 a = __ldg(src), b = __ldg(src + 1);
    float x[NL] = {a.x, a.y, a.z, a.w, b.x, b.y, b.z, b.w};
    float m = x[0];
#pragma unroll
    for (int i = 1; i < NL; i++) m = fmaxf(m, x[i]);

    const float L2E = 1.4426950408889634f;
    float nm = -m * L2E;
    half2 e[4];
#pragma unroll
    for (int i = 0; i < 4; i++) {
        float y0 = fmaf(x[2 * i],     L2E, nm);
        float y1 = fmaf(x[2 * i + 1], L2E, nm);
        e[i] = h2exp2(__floats2half2_rn(y0, y1));
    }
    float sum = 0.f;
#pragma unroll
    for (int i = 0; i < 4; i++) {
        float2 f = __half22float2(e[i]);
        sum += f.x + f.y;
    }
    half2 inv2 = __float2half2_rn(1.f / sum);
    half2 p0 = __hmul2(e[0], inv2), p1 = __hmul2(e[1], inv2);
    half2 p2 = __hmul2(e[2], inv2), p3 = __hmul2(e[3], inv2);
    uint4 o;
    o.x = *reinterpret_cast<unsigned*>(&p0);
    o.y = *reinterpret_cast<unsigned*>(&p1);
    o.z = *reinterpret_cast<unsigned*>(&p2);
    o.w = *reinterpret_cast<unsigned*>(&p3);
    *reinterpret_cast<uint4*>(g_Ph + (size_t)v * NL) = o;
}

// ---------------------------------------------------------------------------
// Uniform-item fused gather. Item i = edges {2i, 2i+1} + triangle {i}:
// 7 row-gathers per thread, identical weight for EVERY thread/block
// (perfect balance, fewer blocks, MLP=7).
// Covers M = min(T, E/2) fused items; leftover tris [M, T) and edges
// [2M, E) go to tail blocks (empty when E == 2T, as in this dataset).
// Blocks [0, fb): fused items. [fb, fb+tb2): leftover tris.
// [fb+tb2, fb+tb2+eb2): leftover edges.
__global__ __launch_bounds__(256)
void gather_kernel(const int* __restrict__ edges, int E,
                   const int* __restrict__ tris,  int T,
                   int M, int fb, int tb2, float* __restrict__ out) {
    float acc = 0.f;
    if ((int)blockIdx.x < fb) {
        int i = blockIdx.x * blockDim.x + threadIdx.x;   // fused item
        if (i < M) {
            int4 e = __ldg(reinterpret_cast<const int4*>(edges) + i);
            int a = __ldg(&tris[3 * i + 0]);
            int b = __ldg(&tris[3 * i + 1]);
            int c = __ldg(&tris[3 * i + 2]);
            uint4 r0 = load_row_raw(e.x);
            uint4 r1 = load_row_raw(e.y);
            uint4 r2 = load_row_raw(e.z);
            uint4 r3 = load_row_raw(e.w);
            uint4 r4 = load_row_raw(a);
            uint4 r5 = load_row_raw(b);
            uint4 r6 = load_row_raw(c);
            acc = -(dot8(r0, r1) + dot8(r2, r3)) + tri_term(r4, r5, r6);
        }
    } else if ((int)blockIdx.x < fb + tb2) {
        int j = (blockIdx.x - fb) * blockDim.x + threadIdx.x + M;
        if (j < T) {
            int a = __ldg(&tris[3 * j + 0]);
            int b = __ldg(&tris[3 * j + 1]);
            int c = __ldg(&tris[3 * j + 2]);
            acc = tri_term(load_row_raw(a), load_row_raw(b), load_row_raw(c));
        }
    } else {
        int k = (blockIdx.x - fb - tb2) * blockDim.x + threadIdx.x + 2 * M;
        if (k < E) {
            int u = __ldg(&edges[2 * k]);
            int w = __ldg(&edges[2 * k + 1]);
            acc = -dot8(load_row_raw(u), load_row_raw(w));
        }
    }
    float tot = block_reduce(acc);
    if (threadIdx.x == 0) atomicAdd(out, tot);
}

// ---------------------------------------------------------------------------
extern "C" void kernel_launch(void* const* d_in, const int* in_sizes, int n_in,
                              void* d_out, int out_size) {
    const float* trainable = (const float*)d_in[0];
    const float* fixedp    = (const float*)d_in[1];
    const int*   fidx      = (const int*)  d_in[2];
    const int*   s1        = (const int*)  d_in[3];
    const int*   s2        = (const int*)  d_in[4];
    float* out = (float*)d_out;

    int n_fixed = in_sizes[2];
    int E = in_sizes[3] / 2;
    int T = in_sizes[4] / 3;

    float base = 2.0f * (float)E + 8.0f * (float)T;

    build_P<<<(NV + 255) / 256, 256>>>(trainable, fixedp, fidx, n_fixed,
                                       out, base);

    int M = (E / 2 < T) ? (E / 2) : T;                 // fused items
    int fb  = (M + 255) / 256;
    int restT = T - M;
    int restE = E - 2 * M;
    int tb2 = (restT + 255) / 256;
    int eb2 = (restE + 255) / 256;
    gather_kernel<<<fb + tb2 + eb2, 256>>>(s1, E, s2, T, M, fb, tb2, out);
}

// round 15
// speedup vs baseline: 1.0236x; 1.0236x over previous
#include <cuda_runtime.h>
#include <cuda_fp16.h>

#define NV 100000
#define NL 8

// P table in fp16: 16 B/row -> one LDG.128 per gather. 1.6 MB, L2-resident.
__device__ __align__(256) __half g_Ph[NV * NL];

// ---------------------------------------------------------------------------
__device__ __forceinline__ float block_reduce(float v) {
    v += __shfl_xor_sync(0xffffffffu, v, 16);
    v += __shfl_xor_sync(0xffffffffu, v, 8);
    v += __shfl_xor_sync(0xffffffffu, v, 4);
    v += __shfl_xor_sync(0xffffffffu, v, 2);
    v += __shfl_xor_sync(0xffffffffu, v, 1);
    __shared__ float s[8];
    int w = threadIdx.x >> 5;
    if ((threadIdx.x & 31) == 0) s[w] = v;
    __syncthreads();
    if (threadIdx.x < 8) {
        v = s[threadIdx.x];
        v += __shfl_xor_sync(0xffu, v, 4);
        v += __shfl_xor_sync(0xffu, v, 2);
        v += __shfl_xor_sync(0xffu, v, 1);
    }
    return v;
}

__device__ __forceinline__ uint4 load_row_raw(int v) {
    return __ldg(reinterpret_cast<const uint4*>(g_Ph + (size_t)v * NL));
}

__device__ __forceinline__ void row_to_f(const uint4& u, float* f) {
    float2 a = __half22float2(*reinterpret_cast<const __half2*>(&u.x));
    float2 b = __half22float2(*reinterpret_cast<const __half2*>(&u.y));
    float2 c = __half22float2(*reinterpret_cast<const __half2*>(&u.z));
    float2 d = __half22float2(*reinterpret_cast<const __half2*>(&u.w));
    f[0] = a.x; f[1] = a.y; f[2] = b.x; f[3] = b.y;
    f[4] = c.x; f[5] = c.y; f[6] = d.x; f[7] = d.y;
}

__device__ __forceinline__ float dot8(const uint4& pu, const uint4& qu) {
    float p[NL], q[NL];
    row_to_f(pu, p); row_to_f(qu, q);
    float d = 0.f;
#pragma unroll
    for (int t = 0; t < NL; t++) d = fmaf(p[t], q[t], d);
    return d;
}

// tri contribution = -4*(p.q + p.r + q.r) + (16/3)*sum_a p_a q_a r_a
__device__ __forceinline__ float tri_term(const uint4& pu, const uint4& qu,
                                          const uint4& ru) {
    float p[NL], q[NL], r[NL];
    row_to_f(pu, p); row_to_f(qu, q); row_to_f(ru, r);
    float s = 0.f, C = 0.f;
#pragma unroll
    for (int t = 0; t < NL; t++) {
        float qr = q[t] * r[t];
        s = fmaf(p[t], q[t] + r[t], s) + qr;
        C = fmaf(p[t], qr, C);
    }
    return fmaf(-4.f, s, (16.f / 3.f) * C);
}

// ---------------------------------------------------------------------------
// Build P = softmax(full, axis=1) in fp16 via h2exp2 (measured-best shape:
// 256 threads/block). Thread 0 seeds out = 2E+8T.
__global__ __launch_bounds__(256)
void build_P(const float* __restrict__ trainable,
             const float* __restrict__ fixedp,
             const int*   __restrict__ fidx,
             int n_fixed, float* __restrict__ out, float base) {
    int v = blockIdx.x * blockDim.x + threadIdx.x;
    if (v == 0) out[0] = base;
    if (v >= NV) return;

    int f0 = __ldg(&fidx[0]);
    int fl = __ldg(&fidx[n_fixed - 1]);
    int lo;
    bool is_fixed;
    if (fl - f0 == n_fixed - 1) {          // contiguous block of fixed ids
        is_fixed = (v >= f0) && (v <= fl);
        lo = is_fixed ? (v - f0) : ((v < f0) ? 0 : n_fixed);
    } else {                               // general sorted unique set
        lo = 0; int hi = n_fixed;
        while (lo < hi) {
            int mid = (lo + hi) >> 1;
            if (__ldg(&fidx[mid]) < v) lo = mid + 1; else hi = mid;
        }
        is_fixed = (lo < n_fixed) && (__ldg(&fidx[lo]) == v);
    }
    const float4* src = reinterpret_cast<const float4*>(
        is_fixed ? (fixedp + (size_t)lo * NL)
                 : (trainable + (size_t)(v - lo) * NL));

    float4 a = __ldg(src), b = __ldg(src + 1);
    float x[NL] = {a.x, a.y, a.z, a.w, b.x, b.y, b.z, b.w};
    float m = x[0];
#pragma unroll
    for (int i = 1; i < NL; i++) m = fmaxf(m, x[i]);

    const float L2E = 1.4426950408889634f;
    float nm = -m * L2E;
    half2 e[4];
#pragma unroll
    for (int i = 0; i < 4; i++) {
        float y0 = fmaf(x[2 * i],     L2E, nm);
        float y1 = fmaf(x[2 * i + 1], L2E, nm);
        e[i] = h2exp2(__floats2half2_rn(y0, y1));
    }
    float sum = 0.f;
#pragma unroll
    for (int i = 0; i < 4; i++) {
        float2 f = __half22float2(e[i]);
        sum += f.x + f.y;
    }
    half2 inv2 = __float2half2_rn(1.f / sum);
    half2 p0 = __hmul2(e[0], inv2), p1 = __hmul2(e[1], inv2);
    half2 p2 = __hmul2(e[2], inv2), p3 = __hmul2(e[3], inv2);
    uint4 o;
    o.x = *reinterpret_cast<unsigned*>(&p0);
    o.y = *reinterpret_cast<unsigned*>(&p1);
    o.z = *reinterpret_cast<unsigned*>(&p2);
    o.w = *reinterpret_cast<unsigned*>(&p3);
    *reinterpret_cast<uint4*>(g_Ph + (size_t)v * NL) = o;
}

// ---------------------------------------------------------------------------
// Uniform-item fused gather. Item i = edges {2i, 2i+1} + triangle {i}:
// 7 row-gathers per thread, identical weight for every thread/block.
// __launch_bounds__(256, 8) caps regs at 32 so 8 blocks/SM fit (R14 got
// regs=34 -> 7 blocks/SM -> occ 65%); wave size 1036 -> 1184.
// Covers M = min(T, E/2) fused items; leftover tris [M, T) and edges
// [2M, E) go to tail blocks (empty when E == 2T, as in this dataset).
// Blocks [0, fb): fused items. [fb, fb+tb2): leftover tris. Then edges.
__global__ __launch_bounds__(256, 8)
void gather_kernel(const int* __restrict__ edges, int E,
                   const int* __restrict__ tris,  int T,
                   int M, int fb, int tb2, float* __restrict__ out) {
    float acc = 0.f;
    if ((int)blockIdx.x < fb) {
        int i = blockIdx.x * blockDim.x + threadIdx.x;   // fused item
        if (i < M) {
            int4 e = __ldg(reinterpret_cast<const int4*>(edges) + i);
            int a = __ldg(&tris[3 * i + 0]);
            int b = __ldg(&tris[3 * i + 1]);
            int c = __ldg(&tris[3 * i + 2]);
            uint4 r0 = load_row_raw(e.x);
            uint4 r1 = load_row_raw(e.y);
            uint4 r2 = load_row_raw(e.z);
            uint4 r3 = load_row_raw(e.w);
            uint4 r4 = load_row_raw(a);
            uint4 r5 = load_row_raw(b);
            uint4 r6 = load_row_raw(c);
            acc = -(dot8(r0, r1) + dot8(r2, r3)) + tri_term(r4, r5, r6);
        }
    } else if ((int)blockIdx.x < fb + tb2) {
        int j = (blockIdx.x - fb) * blockDim.x + threadIdx.x + M;
        if (j < T) {
            int a = __ldg(&tris[3 * j + 0]);
            int b = __ldg(&tris[3 * j + 1]);
            int c = __ldg(&tris[3 * j + 2]);
            acc = tri_term(load_row_raw(a), load_row_raw(b), load_row_raw(c));
        }
    } else {
        int k = (blockIdx.x - fb - tb2) * blockDim.x + threadIdx.x + 2 * M;
        if (k < E) {
            int u = __ldg(&edges[2 * k]);
            int w = __ldg(&edges[2 * k + 1]);
            acc = -dot8(load_row_raw(u), load_row_raw(w));
        }
    }
    float tot = block_reduce(acc);
    if (threadIdx.x == 0) atomicAdd(out, tot);
}

// ---------------------------------------------------------------------------
extern "C" void kernel_launch(void* const* d_in, const int* in_sizes, int n_in,
                              void* d_out, int out_size) {
    const float* trainable = (const float*)d_in[0];
    const float* fixedp    = (const float*)d_in[1];
    const int*   fidx      = (const int*)  d_in[2];
    const int*   s1        = (const int*)  d_in[3];
    const int*   s2        = (const int*)  d_in[4];
    float* out = (float*)d_out;

    int n_fixed = in_sizes[2];
    int E = in_sizes[3] / 2;
    int T = in_sizes[4] / 3;

    float base = 2.0f * (float)E + 8.0f * (float)T;

    build_P<<<(NV + 255) / 256, 256>>>(trainable, fixedp, fidx, n_fixed,
                                       out, base);

    int M = (E / 2 < T) ? (E / 2) : T;                 // fused items
    int fb  = (M + 255) / 256;
    int restT = T - M;
    int restE = E - 2 * M;
    int tb2 = (restT + 255) / 256;
    int eb2 = (restE + 255) / 256;
    gather_kernel<<<fb + tb2 + eb2, 256>>>(s1, E, s2, T, M, fb, tb2, out);
}

// round 16
// speedup vs baseline: 1.1537x; 1.1271x over previous
#include <cuda_runtime.h>
#include <cuda_fp16.h>

#define NV 100000
#define NL 8

// P table in fp16: 16 B/row -> one LDG.128 per gather. 1.6 MB, L2-resident.
__device__ __align__(256) __half g_Ph[NV * NL];

// ---------------------------------------------------------------------------
__device__ __forceinline__ float block_reduce(float v) {
    v += __shfl_xor_sync(0xffffffffu, v, 16);
    v += __shfl_xor_sync(0xffffffffu, v, 8);
    v += __shfl_xor_sync(0xffffffffu, v, 4);
    v += __shfl_xor_sync(0xffffffffu, v, 2);
    v += __shfl_xor_sync(0xffffffffu, v, 1);
    __shared__ float s[8];
    int w = threadIdx.x >> 5;
    if ((threadIdx.x & 31) == 0) s[w] = v;
    __syncthreads();
    if (threadIdx.x < 8) {
        v = s[threadIdx.x];
        v += __shfl_xor_sync(0xffu, v, 4);
        v += __shfl_xor_sync(0xffu, v, 2);
        v += __shfl_xor_sync(0xffu, v, 1);
    }
    return v;
}

__device__ __forceinline__ uint4 load_row_raw(int v) {
    return __ldg(reinterpret_cast<const uint4*>(g_Ph + (size_t)v * NL));
}

__device__ __forceinline__ void row_to_f(const uint4& u, float* f) {
    float2 a = __half22float2(*reinterpret_cast<const __half2*>(&u.x));
    float2 b = __half22float2(*reinterpret_cast<const __half2*>(&u.y));
    float2 c = __half22float2(*reinterpret_cast<const __half2*>(&u.z));
    float2 d = __half22float2(*reinterpret_cast<const __half2*>(&u.w));
    f[0] = a.x; f[1] = a.y; f[2] = b.x; f[3] = b.y;
    f[4] = c.x; f[5] = c.y; f[6] = d.x; f[7] = d.y;
}

__device__ __forceinline__ float dot8(const uint4& pu, const uint4& qu) {
    float p[NL], q[NL];
    row_to_f(pu, p); row_to_f(qu, q);
    float d = 0.f;
#pragma unroll
    for (int t = 0; t < NL; t++) d = fmaf(p[t], q[t], d);
    return d;
}

// tri contribution = -4*(p.q + p.r + q.r) + (16/3)*sum_a p_a q_a r_a
__device__ __forceinline__ float tri_term(const uint4& pu, const uint4& qu,
                                          const uint4& ru) {
    float p[NL], q[NL], r[NL];
    row_to_f(pu, p); row_to_f(qu, q); row_to_f(ru, r);
    float s = 0.f, C = 0.f;
#pragma unroll
    for (int t = 0; t < NL; t++) {
        float qr = q[t] * r[t];
        s = fmaf(p[t], q[t] + r[t], s) + qr;
        C = fmaf(p[t], qr, C);
    }
    return fmaf(-4.f, s, (16.f / 3.f) * C);
}

// ---------------------------------------------------------------------------
// Build P = softmax(full, axis=1) in fp16 via h2exp2 (measured-best shape:
// 256 threads/block). Thread 0 seeds out = 2E+8T.
__global__ __launch_bounds__(256)
void build_P(const float* __restrict__ trainable,
             const float* __restrict__ fixedp,
             const int*   __restrict__ fidx,
             int n_fixed, float* __restrict__ out, float base) {
    int v = blockIdx.x * blockDim.x + threadIdx.x;
    if (v == 0) out[0] = base;
    if (v >= NV) return;

    int f0 = __ldg(&fidx[0]);
    int fl = __ldg(&fidx[n_fixed - 1]);
    int lo;
    bool is_fixed;
    if (fl - f0 == n_fixed - 1) {          // contiguous block of fixed ids
        is_fixed = (v >= f0) && (v <= fl);
        lo = is_fixed ? (v - f0) : ((v < f0) ? 0 : n_fixed);
    } else {                               // general sorted unique set
        lo = 0; int hi = n_fixed;
        while (lo < hi) {
            int mid = (lo + hi) >> 1;
            if (__ldg(&fidx[mid]) < v) lo = mid + 1; else hi = mid;
        }
        is_fixed = (lo < n_fixed) && (__ldg(&fidx[lo]) == v);
    }
    const float4* src = reinterpret_cast<const float4*>(
        is_fixed ? (fixedp + (size_t)lo * NL)
                 : (trainable + (size_t)(v - lo) * NL));

    float4 a = __ldg(src), b = __ldg(src + 1);
    float x[NL] = {a.x, a.y, a.z, a.w, b.x, b.y, b.z, b.w};
    float m = x[0];
#pragma unroll
    for (int i = 1; i < NL; i++) m = fmaxf(m, x[i]);

    const float L2E = 1.4426950408889634f;
    float nm = -m * L2E;
    half2 e[4];
#pragma unroll
    for (int i = 0; i < 4; i++) {
        float y0 = fmaf(x[2 * i],     L2E, nm);
        float y1 = fmaf(x[2 * i + 1], L2E, nm);
        e[i] = h2exp2(__floats2half2_rn(y0, y1));
    }
    float sum = 0.f;
#pragma unroll
    for (int i = 0; i < 4; i++) {
        float2 f = __half22float2(e[i]);
        sum += f.x + f.y;
    }
    half2 inv2 = __float2half2_rn(1.f / sum);
    half2 p0 = __hmul2(e[0], inv2), p1 = __hmul2(e[1], inv2);
    half2 p2 = __hmul2(e[2], inv2), p3 = __hmul2(e[3], inv2);
    uint4 o;
    o.x = *reinterpret_cast<unsigned*>(&p0);
    o.y = *reinterpret_cast<unsigned*>(&p1);
    o.z = *reinterpret_cast<unsigned*>(&p2);
    o.w = *reinterpret_cast<unsigned*>(&p3);
    *reinterpret_cast<uint4*>(g_Ph + (size_t)v * NL) = o;
}

// ---------------------------------------------------------------------------
// Uniform-item fused gather (R14 measured-best gather node: 14.85us).
// Item i = edges {2i, 2i+1} + triangle {i}: 7 row-gathers per thread,
// identical weight for every thread/block. NO min-blocks cap: natural
// regs=34 preserves ptxas's front-batched load schedule (capping to 32
// regs in R15 rematerialized and slowed the kernel to 16.7us).
// Covers M = min(T, E/2) fused items; leftover tris [M, T) and edges
// [2M, E) go to tail blocks (empty when E == 2T, as in this dataset).
// Blocks [0, fb): fused items. [fb, fb+tb2): leftover tris. Then edges.
__global__ __launch_bounds__(256)
void gather_kernel(const int* __restrict__ edges, int E,
                   const int* __restrict__ tris,  int T,
                   int M, int fb, int tb2, float* __restrict__ out) {
    float acc = 0.f;
    if ((int)blockIdx.x < fb) {
        int i = blockIdx.x * blockDim.x + threadIdx.x;   // fused item
        if (i < M) {
            int4 e = __ldg(reinterpret_cast<const int4*>(edges) + i);
            int a = __ldg(&tris[3 * i + 0]);
            int b = __ldg(&tris[3 * i + 1]);
            int c = __ldg(&tris[3 * i + 2]);
            uint4 r0 = load_row_raw(e.x);
            uint4 r1 = load_row_raw(e.y);
            uint4 r2 = load_row_raw(e.z);
            uint4 r3 = load_row_raw(e.w);
            uint4 r4 = load_row_raw(a);
            uint4 r5 = load_row_raw(b);
            uint4 r6 = load_row_raw(c);
            acc = -(dot8(r0, r1) + dot8(r2, r3)) + tri_term(r4, r5, r6);
        }
    } else if ((int)blockIdx.x < fb + tb2) {
        int j = (blockIdx.x - fb) * blockDim.x + threadIdx.x + M;
        if (j < T) {
            int a = __ldg(&tris[3 * j + 0]);
            int b = __ldg(&tris[3 * j + 1]);
            int c = __ldg(&tris[3 * j + 2]);
            acc = tri_term(load_row_raw(a), load_row_raw(b), load_row_raw(c));
        }
    } else {
        int k = (blockIdx.x - fb - tb2) * blockDim.x + threadIdx.x + 2 * M;
        if (k < E) {
            int u = __ldg(&edges[2 * k]);
            int w = __ldg(&edges[2 * k + 1]);
            acc = -dot8(load_row_raw(u), load_row_raw(w));
        }
    }
    float tot = block_reduce(acc);
    if (threadIdx.x == 0) atomicAdd(out, tot);
}

// ---------------------------------------------------------------------------
extern "C" void kernel_launch(void* const* d_in, const int* in_sizes, int n_in,
                              void* d_out, int out_size) {
    const float* trainable = (const float*)d_in[0];
    const float* fixedp    = (const float*)d_in[1];
    const int*   fidx      = (const int*)  d_in[2];
    const int*   s1        = (const int*)  d_in[3];
    const int*   s2        = (const int*)  d_in[4];
    float* out = (float*)d_out;

    int n_fixed = in_sizes[2];
    int E = in_sizes[3] / 2;
    int T = in_sizes[4] / 3;

    float base = 2.0f * (float)E + 8.0f * (float)T;

    build_P<<<(NV + 255) / 256, 256>>>(trainable, fixedp, fidx, n_fixed,
                                       out, base);

    int M = (E / 2 < T) ? (E / 2) : T;                 // fused items
    int fb  = (M + 255) / 256;
    int restT = T - M;
    int restE = E - 2 * M;
    int tb2 = (restT + 255) / 256;
    int eb2 = (restE + 255) / 256;
    gather_kernel<<<fb + tb2 + eb2, 256>>>(s1, E, s2, T, M, fb, tb2, out);
}